// round 1
// baseline (speedup 1.0000x reference)
#include <cuda_runtime.h>

// Problem constants (fixed by the reference)
#define VV   24
#define KK   4
#define HH   224
#define WW   224
#define HWN  50176      // H*W
#define PP   96         // V*K
#define CHUNKS 49       // 50176 / 1024
#define PIXB 1024       // pixels per block
#define THREADS 256     // 4 pixels per thread

// Scratch (no allocations allowed) — fully rewritten every call => deterministic
__device__ float g_part1[PP * CHUNKS];
__device__ float g_fac[PP];
__device__ float g_part2[PP * CHUNKS];

__device__ __forceinline__ float blockReduceSum(float v) {
    __shared__ float sh[32];
    int lane = threadIdx.x & 31;
    int wid  = threadIdx.x >> 5;
#pragma unroll
    for (int o = 16; o; o >>= 1) v += __shfl_down_sync(0xffffffffu, v, o);
    if (lane == 0) sh[wid] = v;
    __syncthreads();
    int nw = (blockDim.x + 31) >> 5;
    v = (wid == 0 && lane < nw) ? sh[lane] : 0.0f;
    if (wid == 0) {
#pragma unroll
        for (int o = 16; o; o >>= 1) v += __shfl_down_sync(0xffffffffu, v, o);
    }
    return v;  // valid on thread 0
}

// ---------------- Pass 1: per-p sum of ||pts_i|| + ||pts_j|| ----------------
__global__ void __launch_bounds__(THREADS)
k_pass1(const float* __restrict__ pts_i, const float* __restrict__ pts_j) {
    int p = blockIdx.y, c = blockIdx.x, t = threadIdx.x;
    size_t base = ((size_t)p * HWN + (size_t)c * PIXB + (size_t)t * 4) * 3;

    const float4* A = (const float4*)(pts_i + base);
    float4 a0 = A[0], a1 = A[1], a2 = A[2];
    const float4* B = (const float4*)(pts_j + base);
    float4 b0 = B[0], b1 = B[1], b2 = B[2];

    float s =
        sqrtf(a0.x*a0.x + a0.y*a0.y + a0.z*a0.z) +
        sqrtf(a0.w*a0.w + a1.x*a1.x + a1.y*a1.y) +
        sqrtf(a1.z*a1.z + a1.w*a1.w + a2.x*a2.x) +
        sqrtf(a2.y*a2.y + a2.z*a2.z + a2.w*a2.w) +
        sqrtf(b0.x*b0.x + b0.y*b0.y + b0.z*b0.z) +
        sqrtf(b0.w*b0.w + b1.x*b1.x + b1.y*b1.y) +
        sqrtf(b1.z*b1.z + b1.w*b1.w + b2.x*b2.x) +
        sqrtf(b2.y*b2.y + b2.z*b2.z + b2.w*b2.w);

    float tot = blockReduceSum(s);
    if (t == 0) g_part1[p * CHUNKS + c] = tot;
}

// ---------------- fac[p] = exp(psl[p]) * 2HW / sum_norms[p] ----------------
__global__ void k_fac(const float* __restrict__ psl) {
    int p = threadIdx.x;
    if (p < PP) {
        float s = 0.0f;
#pragma unroll 7
        for (int c = 0; c < CHUNKS; c++) s += g_part1[p * CHUNKS + c];
        g_fac[p] = __expf(psl[p]) * (2.0f * (float)HWN) / s;
    }
}

// ---------------- Pass 2: loss partial sums ----------------
__global__ void __launch_bounds__(THREADS)
k_pass2(const float* __restrict__ pts_i, const float* __restrict__ pts_j,
        const float* __restrict__ conf_i, const float* __restrict__ conf_j,
        const float* __restrict__ poses, const float* __restrict__ focals,
        const float* __restrict__ pp, const float* __restrict__ dlog,
        const int* __restrict__ v1i, const int* __restrict__ v2i) {
    int p = blockIdx.y, c = blockIdx.x, t = threadIdx.x;

    __shared__ float S[30];
    __shared__ int   sv[2];
    if (t == 0) {
        int v1 = v1i[p], v2 = v2i[p];
        sv[0] = v1; sv[1] = v2;
        float fac = g_fac[p];
        const float* T1 = poses + v1 * 16;
        const float* T2 = poses + v2 * 16;
        // R1f = fac * R1 (row-major 3x3)
        S[0] = fac*T1[0]; S[1] = fac*T1[1]; S[2] = fac*T1[2];
        S[3] = fac*T1[4]; S[4] = fac*T1[5]; S[5] = fac*T1[6];
        S[6] = fac*T1[8]; S[7] = fac*T1[9]; S[8] = fac*T1[10];
        // R2
        S[9]  = T2[0]; S[10] = T2[1]; S[11] = T2[2];
        S[12] = T2[4]; S[13] = T2[5]; S[14] = T2[6];
        S[15] = T2[8]; S[16] = T2[9]; S[17] = T2[10];
        // dt = t2 - t1
        S[18] = T2[3] - T1[3]; S[19] = T2[7] - T1[7]; S[20] = T2[11] - T1[11];
        // intrinsics
        S[21] = pp[v1*2]; S[22] = pp[v1*2+1];
        S[23] = 1.0f / focals[v1*2]; S[24] = 1.0f / focals[v1*2+1];
        S[25] = pp[v2*2]; S[26] = pp[v2*2+1];
        S[27] = 1.0f / focals[v2*2]; S[28] = 1.0f / focals[v2*2+1];
        S[29] = fac;
    }
    __syncthreads();

    int m0 = c * PIXB + t * 4;
    size_t pb = (size_t)p * HWN;

    const float4* A = (const float4*)(pts_i + (pb + (size_t)m0) * 3);
    float4 a0 = A[0], a1 = A[1], a2 = A[2];
    const float4* B = (const float4*)(pts_j + (pb + (size_t)m0) * 3);
    float4 b0 = B[0], b1 = B[1], b2 = B[2];
    float4 ci  = *(const float4*)(conf_i + pb + m0);
    float4 cj  = *(const float4*)(conf_j + pb + m0);
    float4 dl1 = *(const float4*)(dlog + (size_t)sv[0] * HWN + m0);
    float4 dl2 = *(const float4*)(dlog + (size_t)sv[1] * HWN + m0);

    float pix[12] = {a0.x,a0.y,a0.z, a0.w,a1.x,a1.y, a1.z,a1.w,a2.x, a2.y,a2.z,a2.w};
    float pjx[12] = {b0.x,b0.y,b0.z, b0.w,b1.x,b1.y, b1.z,b1.w,b2.x, b2.y,b2.z,b2.w};
    float civ[4] = {ci.x, ci.y, ci.z, ci.w};
    float cjv[4] = {cj.x, cj.y, cj.z, cj.w};
    float d1v[4] = {dl1.x, dl1.y, dl1.z, dl1.w};
    float d2v[4] = {dl2.x, dl2.y, dl2.z, dl2.w};

    float fac = S[29];
    float acc = 0.0f;
#pragma unroll
    for (int k = 0; k < 4; k++) {
        int m = m0 + k;
        int y = m / WW;
        int x = m - y * WW;
        float fx = (float)x, fy = (float)y;

        // ---- term i: ||cam1 - fac*pts_i|| (rotation dropped: norm-invariant)
        float d1 = __expf(d1v[k]);
        float cx = d1 * (fx - S[21]) * S[23];
        float cy = d1 * (fy - S[22]) * S[24];
        float ex = cx - fac * pix[3*k+0];
        float ey = cy - fac * pix[3*k+1];
        float ez = d1 - fac * pix[3*k+2];
        acc += sqrtf(ex*ex + ey*ey + ez*ez) * __logf(civ[k]);

        // ---- term j: ||R2*cam2 - R1f*pts_j + (t2 - t1)||
        float d2  = __expf(d2v[k]);
        float c2x = d2 * (fx - S[25]) * S[27];
        float c2y = d2 * (fy - S[26]) * S[28];
        float ox = S[9]*c2x  + S[10]*c2y + S[11]*d2;
        float oy = S[12]*c2x + S[13]*c2y + S[14]*d2;
        float oz = S[15]*c2x + S[16]*c2y + S[17]*d2;
        float px3 = pjx[3*k+0], py3 = pjx[3*k+1], pz3 = pjx[3*k+2];
        float qx = S[0]*px3 + S[1]*py3 + S[2]*pz3;
        float qy = S[3]*px3 + S[4]*py3 + S[5]*pz3;
        float qz = S[6]*px3 + S[7]*py3 + S[8]*pz3;
        float gx = ox - qx + S[18];
        float gy = oy - qy + S[19];
        float gz = oz - qz + S[20];
        acc += sqrtf(gx*gx + gy*gy + gz*gz) * __logf(cjv[k]);
    }

    float tot = blockReduceSum(acc);
    if (t == 0) g_part2[p * CHUNKS + c] = tot;
}

// ---------------- Final deterministic reduce ----------------
__global__ void k_final(float* __restrict__ out) {
    int t = threadIdx.x;
    float s = 0.0f;
    for (int i = t; i < PP * CHUNKS; i += 1024) s += g_part2[i];
    float tot = blockReduceSum(s);
    if (t == 0) out[0] = tot * (1.0f / ((float)PP * (float)HWN));
}

extern "C" void kernel_launch(void* const* d_in, const int* in_sizes, int n_in,
                              void* d_out, int out_size) {
    const float* pts3d_i   = (const float*)d_in[0];
    const float* pts3d_j   = (const float*)d_in[1];
    const float* conf_i    = (const float*)d_in[2];
    const float* conf_j    = (const float*)d_in[3];
    const float* poses     = (const float*)d_in[4];
    const float* focals    = (const float*)d_in[5];
    const float* pp        = (const float*)d_in[6];
    // d_in[7] = pixels : recomputed analytically, not loaded
    const float* depth_log = (const float*)d_in[8];
    const float* psl       = (const float*)d_in[9];
    const int*   v1i       = (const int*)d_in[10];
    const int*   v2i       = (const int*)d_in[11];
    float* out = (float*)d_out;

    dim3 grid(CHUNKS, PP);
    k_pass1<<<grid, THREADS>>>(pts3d_i, pts3d_j);
    k_fac<<<1, 128>>>(psl);
    k_pass2<<<grid, THREADS>>>(pts3d_i, pts3d_j, conf_i, conf_j,
                               poses, focals, pp, depth_log, v1i, v2i);
    k_final<<<1, 1024>>>(out);
}